// round 17
// baseline (speedup 1.0000x reference)
#include <cuda_runtime.h>
#include <cstdint>

#define NPTS   131072          // B*N = 2*65536
#define EPSBN  1e-5f
#define LOG2E  1.4426950408889634f

// ---- fragment-ordered weight tables + folded params (device globals) ----
__device__ __align__(16) uint4  d_fragRaw[4*32];     // raw mlp bf16 3-split: K=16(pad of 10), N=32
__device__ __align__(16) uint2  d_fragR2[16*32];     // W_nb bottom fp16: K=32 (2 kc), N=64 (8 nt)
__device__ __align__(16) uint2  d_fragS2[32*32];     // w_attn*log2e fp16: K=64 (4 kc), N=64 (8 nt)
__device__ __align__(16) uint4  d_fragOut[32*32];    // w_out folded bf16 3-split
__device__ __align__(16) uint4  d_fragGt[16*32];     // W_nb top folded bf16 3-split: K=32, N=64
__device__ __align__(16) uint4  d_fragSc[16*32];     // w_sc folded bf16 3-split: K=32, N=64
__device__ __align__(16) float  d_braw[32];
__device__ __align__(16) float  d_bnb[64];
__device__ __align__(16) float  d_boutN[64];
__device__ __align__(16) float  d_bscN[64];
__device__ __align__(16) float  d_G[(size_t)NPTS*64];  // feature @ W_nb_top' + bnb (~33.5MB)
__device__ __align__(16) float  d_SC[(size_t)NPTS*64]; // feature @ w_sc' + b_sc'   (~33.5MB)
__device__ __align__(16) float  d_P[(size_t)NPTS*64];  // pooled                    (~33.5MB)

__device__ __forceinline__ float lrelu(float x){ return fmaxf(x, 0.2f*x); }
__device__ __forceinline__ float ex2(float x){
    float y; asm("ex2.approx.f32 %0, %1;" : "=f"(y) : "f"(x)); return y;
}

// ---- bf16 3-split helpers ----
__device__ __forceinline__ uint32_t pack_bf16x2(float lo, float hi){
    uint32_t r; asm("cvt.rn.bf16x2.f32 %0, %1, %2;" : "=r"(r) : "f"(hi), "f"(lo)); return r;
}
__device__ __forceinline__ void split_pair(float x0, float x1, uint32_t& ah, uint32_t& al){
    ah = pack_bf16x2(x0, x1);
    float h0 = __uint_as_float(ah << 16);
    float h1 = __uint_as_float(ah & 0xFFFF0000u);
    al = pack_bf16x2(x0 - h0, x1 - h1);
}
__device__ __forceinline__ void mma_bf16(float* d, const uint32_t* a, uint32_t b0, uint32_t b1){
    asm volatile("mma.sync.aligned.m16n8k16.row.col.f32.bf16.bf16.f32 "
        "{%0,%1,%2,%3},{%4,%5,%6,%7},{%8,%9},{%0,%1,%2,%3};"
        : "+f"(d[0]),"+f"(d[1]),"+f"(d[2]),"+f"(d[3])
        : "r"(a[0]),"r"(a[1]),"r"(a[2]),"r"(a[3]),"r"(b0),"r"(b1));
}
__device__ __forceinline__ void mma3(float* d, const uint32_t* ah, const uint32_t* al, uint4 b){
    mma_bf16(d, ah, b.x, b.y);
    mma_bf16(d, al, b.x, b.y);
    mma_bf16(d, ah, b.z, b.w);
}

// ---- fp16 2-split helpers (R + s GEMMs): A = Ah+Al (fp16), B = fp16 ----
__device__ __forceinline__ uint32_t pack_f16x2(float lo, float hi){
    uint32_t r; asm("cvt.rn.f16x2.f32 %0, %1, %2;" : "=r"(r) : "f"(hi), "f"(lo)); return r;
}
__device__ __forceinline__ float2 f16x2_to_f32(uint32_t v){
    float lo, hi;
    asm("{.reg .f16 l, h;\n\t mov.b32 {l, h}, %2;\n\t"
        "cvt.f32.f16 %0, l;\n\t cvt.f32.f16 %1, h;}" : "=f"(lo), "=f"(hi) : "r"(v));
    return make_float2(lo, hi);
}
__device__ __forceinline__ void split_pair_f16(float x0, float x1, uint32_t& ah, uint32_t& al){
    ah = pack_f16x2(x0, x1);
    float2 h = f16x2_to_f32(ah);
    al = pack_f16x2(x0 - h.x, x1 - h.y);
}
__device__ __forceinline__ void mma_f16(float* d, const uint32_t* a, uint32_t b0, uint32_t b1){
    asm volatile("mma.sync.aligned.m16n8k16.row.col.f32.f16.f16.f32 "
        "{%0,%1,%2,%3},{%4,%5,%6,%7},{%8,%9},{%0,%1,%2,%3};"
        : "+f"(d[0]),"+f"(d[1]),"+f"(d[2]),"+f"(d[3])
        : "r"(a[0]),"r"(a[1]),"r"(a[2]),"r"(a[3]),"r"(b0),"r"(b1));
}
__device__ __forceinline__ void mma2(float* d, const uint32_t* ah, const uint32_t* al, uint2 b){
    mma_f16(d, ah, b.x, b.y);
    mma_f16(d, al, b.x, b.y);
}
__device__ __forceinline__ void dfrags_to_afrags_f16(const float* dA, const float* dB,
                                                     uint32_t* ah, uint32_t* al){
    split_pair_f16(dA[0], dA[1], ah[0], al[0]);
    split_pair_f16(dA[2], dA[3], ah[1], al[1]);
    split_pair_f16(dB[0], dB[1], ah[2], al[2]);
    split_pair_f16(dB[2], dB[3], ah[3], al[3]);
}

// ---- Kernel 0: fold BN into weights; 4 blocks, one section each. ----
__global__ void __launch_bounds__(1024) fold_kernel(
    const float* w_raw, const float* b_raw, const float* g_raw, const float* be_raw,
    const float* m_raw, const float* v_raw,
    const float* w_nb,  const float* b_nb,  const float* g_nb,  const float* be_nb,
    const float* m_nb,  const float* v_nb,  const float* w_attn,
    const float* w_out, const float* b_out, const float* g_out, const float* be_out,
    const float* m_out, const float* v_out,
    const float* w_sc,  const float* b_sc,  const float* g_sc,  const float* be_sc,
    const float* m_sc,  const float* v_sc)
{
    const int t0 = threadIdx.x;
    const int lane = t0 & 31, gg = lane >> 2, tt = lane & 3;
    const int sec = blockIdx.x;

    if (sec == 0){
        // fragRaw (bf16 3-split): 128 entries (nt 0..3); k>=10 -> 0
        if (t0 < 128){
            int nt = t0 >> 5, n = nt*8 + gg;
            float sn = g_raw[n]*rsqrtf(v_raw[n]+EPSBN);
            int k0 = 2*tt, k2 = 2*tt + 8;
            float w0 = w_raw[k0*32+n]*sn;
            float w1 = w_raw[(k0+1)*32+n]*sn;
            float w2 = (k2   < 10) ? w_raw[k2*32+n]*sn     : 0.f;
            float w3 = (k2+1 < 10) ? w_raw[(k2+1)*32+n]*sn : 0.f;
            uint32_t h0,l0,h1,l1; split_pair(w0,w1,h0,l0); split_pair(w2,w3,h1,l1);
            d_fragRaw[t0] = make_uint4(h0,h1,l0,l1);
        }
        // fragR2 (fp16): 512 entries (entry = kc*8+nt)
        if (t0 < 512){
            int entry = t0 >> 5, nt = entry & 7, kc = entry >> 3, n = nt*8 + gg;
            float sn = g_nb[n]*rsqrtf(v_nb[n]+EPSBN);
            int k0 = kc*16 + 2*tt;
            float w0 = w_nb[(32+k0)*64+n]*sn,   w1 = w_nb[(32+k0+1)*64+n]*sn;
            float w2 = w_nb[(32+k0+8)*64+n]*sn, w3 = w_nb[(32+k0+9)*64+n]*sn;
            d_fragR2[t0] = make_uint2(pack_f16x2(w0,w1), pack_f16x2(w2,w3));
        }
        // biases
        if (t0 < 64){
            int p = t0;
            float s = g_nb[p]*rsqrtf(v_nb[p]+EPSBN);
            d_bnb[p] = (b_nb[p]-m_nb[p])*s + be_nb[p];
            float so = g_out[p]*rsqrtf(v_out[p]+EPSBN);
            d_boutN[p] = (b_out[p]-m_out[p])*so + be_out[p];
            float ss = g_sc[p]*rsqrtf(v_sc[p]+EPSBN);
            d_bscN[p] = (b_sc[p]-m_sc[p])*ss + be_sc[p];
        }
        if (t0 < 32){
            int p = t0;
            float sr = g_raw[p]*rsqrtf(v_raw[p]+EPSBN);
            d_braw[p] = (b_raw[p]-m_raw[p])*sr + be_raw[p];
        }
    } else if (sec == 1){
        // fragGt + fragSc (bf16 3-split, K=32 -> kc 0..1): 512 entries each
        if (t0 < 512){
            int entry = t0 >> 5, nt = entry & 7, kc = entry >> 3, n = nt*8 + gg;
            int k0 = kc*16 + 2*tt;
            float sg = g_nb[n]*rsqrtf(v_nb[n]+EPSBN);
            float g0 = w_nb[k0*64+n]*sg,     g1 = w_nb[(k0+1)*64+n]*sg;
            float g2 = w_nb[(k0+8)*64+n]*sg, g3 = w_nb[(k0+9)*64+n]*sg;
            uint32_t h0,l0,h1,l1; split_pair(g0,g1,h0,l0); split_pair(g2,g3,h1,l1);
            d_fragGt[t0] = make_uint4(h0,h1,l0,l1);
            float ssn = g_sc[n]*rsqrtf(v_sc[n]+EPSBN);
            float c0 = w_sc[k0*64+n]*ssn,     c1 = w_sc[(k0+1)*64+n]*ssn;
            float c2 = w_sc[(k0+8)*64+n]*ssn, c3 = w_sc[(k0+9)*64+n]*ssn;
            split_pair(c0,c1,h0,l0); split_pair(c2,c3,h1,l1);
            d_fragSc[t0] = make_uint4(h0,h1,l0,l1);
        }
    } else if (sec == 2){
        // fragS2 (fp16, prescaled by log2e): 1024 entries
        int entry = t0 >> 5, nt = entry & 7, kc = entry >> 3, n = nt*8 + gg;
        int k0 = kc*16 + 2*tt;
        float w0 = w_attn[k0*64+n]*LOG2E,     w1 = w_attn[(k0+1)*64+n]*LOG2E;
        float w2 = w_attn[(k0+8)*64+n]*LOG2E, w3 = w_attn[(k0+9)*64+n]*LOG2E;
        d_fragS2[t0] = make_uint2(pack_f16x2(w0,w1), pack_f16x2(w2,w3));
    } else {
        // fragOut (bf16 3-split): 1024 entries, folded w_out
        int entry = t0 >> 5, nt = entry & 7, kc = entry >> 3, n = nt*8 + gg;
        float sn = g_out[n]*rsqrtf(v_out[n]+EPSBN);
        int k0 = kc*16 + 2*tt;
        float w0 = w_out[k0*64+n]*sn,     w1 = w_out[(k0+1)*64+n]*sn;
        float w2 = w_out[(k0+8)*64+n]*sn, w3 = w_out[(k0+9)*64+n]*sn;
        uint32_t h0,l0,h1,l1; split_pair(w0,w1,h0,l0); split_pair(w2,w3,h1,l1);
        d_fragOut[t0] = make_uint4(h0,h1,l0,l1);
    }
}

// ---- Kernel 1 (HMMA): G = feature@Wtop' + bnb ; SC = feature@w_sc' + b_sc'. 16 pts/warp. ----
__global__ void __launch_bounds__(256) g_kernel(const float* __restrict__ feature)
{
    const int tid = threadIdx.x, lane = tid & 31, w = tid >> 5;
    const int g = lane >> 2, t = lane & 3;
    const int ptb = (blockIdx.x*8 + w)*16;

    const float2* F0 = (const float2*)feature + (size_t)(ptb+g)*16;
    const float2* F1 = (const float2*)feature + (size_t)(ptb+g+8)*16;

    float DG[8][4], DS[8][4];
    #pragma unroll
    for (int nt=0;nt<8;nt++){
        float2 bg = *(const float2*)&d_bnb[nt*8 + 2*t];
        float2 bs = *(const float2*)&d_bscN[nt*8 + 2*t];
        DG[nt][0]=bg.x; DG[nt][1]=bg.y; DG[nt][2]=bg.x; DG[nt][3]=bg.y;
        DS[nt][0]=bs.x; DS[nt][1]=bs.y; DS[nt][2]=bs.x; DS[nt][3]=bs.y;
    }
    uint32_t ah[4], al[4];
    #pragma unroll
    for (int kc=0;kc<2;kc++){
        float2 p0 = F0[kc*8 + t];
        float2 p1 = F1[kc*8 + t];
        float2 p2 = F0[kc*8 + t + 4];
        float2 p3 = F1[kc*8 + t + 4];
        split_pair(p0.x, p0.y, ah[0], al[0]);
        split_pair(p1.x, p1.y, ah[1], al[1]);
        split_pair(p2.x, p2.y, ah[2], al[2]);
        split_pair(p3.x, p3.y, ah[3], al[3]);
        #pragma unroll
        for (int nt=0;nt<8;nt++){
            mma3(DG[nt], ah, al, d_fragGt[(kc*8+nt)*32 + lane]);
            mma3(DS[nt], ah, al, d_fragSc[(kc*8+nt)*32 + lane]);
        }
    }
    #pragma unroll
    for (int nt=0;nt<8;nt++){
        int c = nt*8 + 2*t;
        *(float2*)&d_G[(size_t)(ptb+g)*64   + c] = make_float2(DG[nt][0], DG[nt][1]);
        *(float2*)&d_G[(size_t)(ptb+g+8)*64 + c] = make_float2(DG[nt][2], DG[nt][3]);
        *(float2*)&d_SC[(size_t)(ptb+g)*64   + c] = make_float2(DS[nt][0], DS[nt][1]);
        *(float2*)&d_SC[(size_t)(ptb+g+8)*64 + c] = make_float2(DS[nt][2], DS[nt][3]);
    }
}

// ---- Kernel 2: fused main. One warp/point; occupancy 6 via h-reconstruction. ----
__global__ void __launch_bounds__(128, 6) main_kernel(
    const float* __restrict__ raw,
    const int*   __restrict__ nbr)
{
    const int tid = threadIdx.x, lane = tid & 31, w = tid >> 5;
    const int g = lane >> 2, t = lane & 3;

    const int pt = blockIdx.x*4 + w;
    const int bbase = (pt >> 16) << 16;     // batch offset (N=65536)

    int idxv = 0;
    if (lane < 16) idxv = nbr[pt*16 + lane];
    const int jr0 = __shfl_sync(0xffffffffu, idxv, g);
    const int jr1 = __shfl_sync(0xffffffffu, idxv, g+8);

    // ---- raw A-frags straight from gmem (bf16 3-split) ----
    const float2* raw2 = (const float2*)raw + (size_t)pt*80;
    uint32_t ah[4], al[4];
    {
        float2 p0 = raw2[g*5 + t];
        float2 p1 = raw2[(g+8)*5 + t];
        float2 p2 = (t==0) ? raw2[g*5 + 4]     : make_float2(0.f,0.f);
        float2 p3 = (t==0) ? raw2[(g+8)*5 + 4] : make_float2(0.f,0.f);
        split_pair(p0.x, p0.y, ah[0], al[0]);
        split_pair(p1.x, p1.y, ah[1], al[1]);
        split_pair(p2.x, p2.y, ah[2], al[2]);
        split_pair(p3.x, p3.y, ah[3], al[3]);
    }

    // ---- gather G directly into hv accumulators (G carries bnb) ----
    float hv[8][4];
    {
        const float* G0 = d_G + (size_t)(bbase + jr0)*64;
        const float* G1 = d_G + (size_t)(bbase + jr1)*64;
        #pragma unroll
        for (int nt=0;nt<8;nt++){
            float2 a = *(const float2*)&G0[nt*8 + 2*t];
            float2 b = *(const float2*)&G1[nt*8 + 2*t];
            hv[nt][0]=a.x; hv[nt][1]=a.y; hv[nt][2]=b.x; hv[nt][3]=b.y;
        }
    }

    // ---- raw mlp: rmD(16x32) = raw(16x16) @ Wraw + braw; lrelu in place ----
    float rmD[4][4];
    #pragma unroll
    for (int nt=0;nt<4;nt++){
        float2 b = *(const float2*)&d_braw[nt*8 + 2*t];
        rmD[nt][0]=b.x; rmD[nt][1]=b.y; rmD[nt][2]=b.x; rmD[nt][3]=b.y;
    }
    #pragma unroll
    for (int nt=0;nt<4;nt++)
        mma3(rmD[nt], ah, al, d_fragRaw[nt*32 + lane]);
    #pragma unroll
    for (int nt=0;nt<4;nt++)
        #pragma unroll
        for (int i=0;i<4;i++) rmD[nt][i] = lrelu(rmD[nt][i]);

    // ---- R-GEMM (fp16 2-split): hv += rm(16x32) @ W_nbb ----
    #pragma unroll
    for (int kc=0;kc<2;kc++){
        dfrags_to_afrags_f16(rmD[2*kc], rmD[2*kc+1], ah, al);
        #pragma unroll
        for (int nt=0;nt<8;nt++)
            mma2(hv[nt], ah, al, d_fragR2[(kc*8+nt)*32 + lane]);
    }

    // ---- h = lrelu(hv); split to fp16 A-frags; hv dies here (regs freed) ----
    uint32_t sah[4][4], sal[4][4];
    #pragma unroll
    for (int nt=0;nt<8;nt++)
        #pragma unroll
        for (int i=0;i<4;i++) hv[nt][i] = lrelu(hv[nt][i]);
    #pragma unroll
    for (int kc=0;kc<4;kc++)
        dfrags_to_afrags_f16(hv[2*kc], hv[2*kc+1], sah[kc], sal[kc]);

    // ---- s-GEMM per nt (fp16 2-split, prescaled log2e); h reconstructed from frags ----
    float Kd[8], Kn[8];
    const bool gb0 = (lane & 4) != 0;
    #pragma unroll
    for (int nt=0;nt<8;nt++){
        float sd[4] = {0.f, 0.f, 0.f, 0.f};
        #pragma unroll
        for (int kc=0;kc<4;kc++)
            mma2(sd, sah[kc], sal[kc], d_fragS2[(kc*8+nt)*32 + lane]);
        // reconstruct h values for this nt from the A-fragments (err ~2^-22)
        const int kk = nt >> 1, sel = (nt & 1) ? 2 : 0;
        float2 a0 = f16x2_to_f32(sah[kk][sel]),   b0 = f16x2_to_f32(sal[kk][sel]);
        float2 a1 = f16x2_to_f32(sah[kk][sel+1]), b1 = f16x2_to_f32(sal[kk][sel+1]);
        float h0 = a0.x + b0.x, h1 = a0.y + b0.y;
        float h2 = a1.x + b1.x, h3 = a1.y + b1.y;
        float e0=ex2(sd[0]), e1=ex2(sd[1]), e2=ex2(sd[2]), e3=ex2(sd[3]);
        float den0 = e0+e2, num0 = fmaf(e0, h0, e2*h2);
        float den1 = e1+e3, num1 = fmaf(e1, h1, e3*h3);
        float sdd = gb0 ? den0 : den1;
        float snn = gb0 ? num0 : num1;
        float rd = __shfl_xor_sync(0xffffffffu, sdd, 4);
        float rn = __shfl_xor_sync(0xffffffffu, snn, 4);
        Kd[nt] = (gb0 ? den1 : den0) + rd;
        Kn[nt] = (gb0 ? num1 : num0) + rn;
    }
    const bool gb1 = (lane & 8) != 0;
    float Ld[4], Ln[4];
    #pragma unroll
    for (int j=0;j<4;j++){
        float sd = gb1 ? Kd[j] : Kd[j+4];
        float sn = gb1 ? Kn[j] : Kn[j+4];
        float rd = __shfl_xor_sync(0xffffffffu, sd, 8);
        float rn = __shfl_xor_sync(0xffffffffu, sn, 8);
        Ld[j] = (gb1 ? Kd[j+4] : Kd[j]) + rd;
        Ln[j] = (gb1 ? Kn[j+4] : Kn[j]) + rn;
    }
    const bool gb2 = (lane & 16) != 0;
    #pragma unroll
    for (int j=0;j<2;j++){
        float sd = gb2 ? Ld[j] : Ld[j+2];
        float sn = gb2 ? Ln[j] : Ln[j+2];
        float rd = __shfl_xor_sync(0xffffffffu, sd, 16);
        float rn = __shfl_xor_sync(0xffffffffu, sn, 16);
        float md = (gb2 ? Ld[j+2] : Ld[j]) + rd;
        float mn = (gb2 ? Ln[j+2] : Ln[j]) + rn;
        int nt = j + (gb2 ? 2 : 0) + (gb1 ? 4 : 0);
        int c  = nt*8 + 2*t + (gb0 ? 1 : 0);
        d_P[(size_t)pt*64 + c] = __fdividef(mn, md);
    }
}

// ---- Kernel 3: out = lrelu(SC + pooled @ w_out' + b_out'). N-split: 4 nt/warp. ----
__global__ void __launch_bounds__(256) out_kernel(float* __restrict__ outp)
{
    const int tid = threadIdx.x, lane = tid & 31, w = tid >> 5;
    const int g = lane >> 2, t = lane & 3;
    const int par = blockIdx.x & 1;                 // N half: nt in [4*par, 4*par+4)
    const int ptb = ((blockIdx.x >> 1)*8 + w)*16;

    const float2* P0 = (const float2*)(d_P + (size_t)(ptb+g)*64);
    const float2* P1 = (const float2*)(d_P + (size_t)(ptb+g+8)*64);

    float D[4][4];
    #pragma unroll
    for (int nt=0;nt<4;nt++){
        float2 b = *(const float2*)&d_boutN[(nt+4*par)*8 + 2*t];
        D[nt][0]=b.x; D[nt][1]=b.y; D[nt][2]=b.x; D[nt][3]=b.y;
    }
    uint32_t ah[4], al[4];
    #pragma unroll
    for (int kc=0;kc<4;kc++){
        float2 p0 = P0[kc*8 + t];
        float2 p1 = P1[kc*8 + t];
        float2 p2 = P0[kc*8 + t + 4];
        float2 p3 = P1[kc*8 + t + 4];
        split_pair(p0.x, p0.y, ah[0], al[0]);
        split_pair(p1.x, p1.y, ah[1], al[1]);
        split_pair(p2.x, p2.y, ah[2], al[2]);
        split_pair(p3.x, p3.y, ah[3], al[3]);
        #pragma unroll
        for (int nt=0;nt<4;nt++)
            mma3(D[nt], ah, al, d_fragOut[(kc*8 + nt + 4*par)*32 + lane]);
    }
    const float* S0 = d_SC + (size_t)(ptb+g)*64;
    const float* S1 = d_SC + (size_t)(ptb+g+8)*64;
    #pragma unroll
    for (int nt=0;nt<4;nt++){
        int c = (nt+4*par)*8 + 2*t;
        float2 s0 = *(const float2*)&S0[c];
        float2 s1 = *(const float2*)&S1[c];
        *(float2*)&outp[(size_t)(ptb+g)*64   + c] =
            make_float2(lrelu(D[nt][0] + s0.x), lrelu(D[nt][1] + s0.y));
        *(float2*)&outp[(size_t)(ptb+g+8)*64 + c] =
            make_float2(lrelu(D[nt][2] + s1.x), lrelu(D[nt][3] + s1.y));
    }
}

extern "C" void kernel_launch(void* const* d_in, const int* in_sizes, int n_in,
                              void* d_out, int out_size)
{
    const float* feature = (const float*)d_in[0];
    const float* raw     = (const float*)d_in[1];
    const int*   nbr     = (const int*)  d_in[2];

    fold_kernel<<<4, 1024>>>(
        (const float*)d_in[3],  (const float*)d_in[4],  (const float*)d_in[5],
        (const float*)d_in[6],  (const float*)d_in[7],  (const float*)d_in[8],
        (const float*)d_in[9],  (const float*)d_in[10], (const float*)d_in[11],
        (const float*)d_in[12], (const float*)d_in[13], (const float*)d_in[14],
        (const float*)d_in[15],
        (const float*)d_in[16], (const float*)d_in[17], (const float*)d_in[18],
        (const float*)d_in[19], (const float*)d_in[20], (const float*)d_in[21],
        (const float*)d_in[22], (const float*)d_in[23], (const float*)d_in[24],
        (const float*)d_in[25], (const float*)d_in[26], (const float*)d_in[27]);

    g_kernel<<<NPTS/(16*8), 256>>>(feature);

    main_kernel<<<NPTS/4, 128>>>(raw, nbr);

    out_kernel<<<NPTS/(16*8)*2, 256>>>((float*)d_out);
}